// round 13
// baseline (speedup 1.0000x reference)
#include <cuda_runtime.h>

__device__ __forceinline__ float frcp(float x){ float y; asm("rcp.approx.ftz.f32 %0,%1;":"=f"(y):"f"(x)); return y; }
__device__ __forceinline__ float fex2(float x){ float y; asm("ex2.approx.ftz.f32 %0,%1;":"=f"(y):"f"(x)); return y; }
__device__ __forceinline__ float flg2(float x){ float y; asm("lg2.approx.ftz.f32 %0,%1;":"=f"(y):"f"(x)); return y; }

#define FM 0xFFFFFFFFu

#define DECL_SLOT(S) float hb##S##0, hd##S##0, hb##S##1, hd##S##1, z##S##0, z##S##1;

// Prefetch one padded row (b,d,z) into pfb/pfd/pfz.
#define LOADROW(g) do { \
    const int gg = (g); \
    const bool p = ((unsigned)gg < 1024u) & colok; \
    const size_t off = (size_t)gg << 10; \
    pfb = p ? *(const float2*)(pb + off) : make_float2(0.f, 0.f); \
    pfd = p ? *(const float2*)(pd + off) : make_float2(0.f, 0.f); \
    pfz = p ? *(const float2*)(pz + off) : make_float2(0.f, 0.f); \
} while(0)

// Horizontal blur of prefetched row (pfb/pfd/pfz), deposit into slot S.
#define STEPC(S, g) do { \
    const bool yin = (unsigned)(g) < 1024u; \
    const float bx=pfb.x, by=pfb.y, dx=pfd.x, dy=pfd.y, zx=pfz.x, zy=pfz.y; \
    const float blx = __shfl_up_sync(FM, bx, 1); \
    const float bly = __shfl_up_sync(FM, by, 1); \
    const float dlx = __shfl_up_sync(FM, dx, 1); \
    const float dly = __shfl_up_sync(FM, dy, 1); \
    const float zlx = __shfl_up_sync(FM, zx, 1); \
    const float zly = __shfl_up_sync(FM, zy, 1); \
    const float brx = __shfl_down_sync(FM, bx, 1); \
    const float bry = __shfl_down_sync(FM, by, 1); \
    const float drx = __shfl_down_sync(FM, dx, 1); \
    const float dry = __shfl_down_sync(FM, dy, 1); \
    const float zrx = __shfl_down_sync(FM, zx, 1); \
    const float zry = __shfl_down_sync(FM, zy, 1); \
    { /* px0 */ \
      const float rz = frcp(zx); \
      float u, a, w; \
      u = fmaf(zlx, rz, -1.f); a = __saturatef(u*u); w = fex2(fmaf(a, c2l, sw0)); \
      float ws = w, bs = w*blx, ds = w*dlx; \
      u = fmaf(zly, rz, -1.f); a = __saturatef(u*u); w = fex2(fmaf(a, c2l, sw1)); \
      ws += w; bs = fmaf(w, bly, bs); ds = fmaf(w, dly, ds); \
      ws += 1.f; bs += bx; ds += dx; /* center tap: w == 1 exactly */ \
      u = fmaf(zy, rz, -1.f); a = __saturatef(u*u); w = fex2(fmaf(a, c2l, sw1)); \
      ws += w; bs = fmaf(w, by, bs); ds = fmaf(w, dy, ds); \
      u = fmaf(zrx, rz, -1.f); a = __saturatef(u*u); w = fex2(fmaf(a, c2l, sw0)); \
      ws += w; bs = fmaf(w, brx, bs); ds = fmaf(w, drx, ds); \
      const float wi = yin ? frcp(ws) : 0.f; \
      hb##S##0 = bs * wi; hd##S##0 = ds * wi; } \
    { /* px1 */ \
      const float rz = frcp(zy); \
      float u, a, w; \
      u = fmaf(zly, rz, -1.f); a = __saturatef(u*u); w = fex2(fmaf(a, c2l, sw0)); \
      float ws = w, bs = w*bly, ds = w*dly; \
      u = fmaf(zx, rz, -1.f); a = __saturatef(u*u); w = fex2(fmaf(a, c2l, sw1)); \
      ws += w; bs = fmaf(w, bx, bs); ds = fmaf(w, dx, ds); \
      ws += 1.f; bs += by; ds += dy; \
      u = fmaf(zrx, rz, -1.f); a = __saturatef(u*u); w = fex2(fmaf(a, c2l, sw1)); \
      ws += w; bs = fmaf(w, brx, bs); ds = fmaf(w, drx, ds); \
      u = fmaf(zry, rz, -1.f); a = __saturatef(u*u); w = fex2(fmaf(a, c2l, sw0)); \
      ws += w; bs = fmaf(w, bry, bs); ds = fmaf(w, dry, ds); \
      const float wi = yin ? frcp(ws) : 0.f; \
      hb##S##1 = bs * wi; hd##S##1 = ds * wi; } \
    z##S##0 = zx; z##S##1 = zy; \
} while(0)

// Vertical blur + blend + store for output row g. Center b/d loaded here
// (L1-hit: lines fetched by LOADROW(g) several phases earlier). All slot
// inputs were produced >= 2 full phases ago -> independent of the
// same-phase and previous-phase STEPC.
#define EMIT(S0,S1,S2,S3,S4, g) do { \
    const int gg = (g); \
    const bool yin = (unsigned)gg < 1024u; \
    const size_t off = (size_t)gg << 10; \
    const bool cp = yin & colok; \
    const float2 cb = cp ? *(const float2*)(pb + off) : make_float2(0.f, 0.f); \
    const float2 cd = cp ? *(const float2*)(pd + off) : make_float2(0.f, 0.f); \
    float o0, o1; \
    { const float rz = frcp(z##S2##0); \
      float u, a, w; \
      u = fmaf(z##S0##0, rz, -1.f); a = __saturatef(u*u); w = fex2(fmaf(a, c2l, sw0)); \
      float ws = w, bs = w*hb##S0##0, ds = w*hd##S0##0; \
      u = fmaf(z##S1##0, rz, -1.f); a = __saturatef(u*u); w = fex2(fmaf(a, c2l, sw1)); \
      ws += w; bs = fmaf(w, hb##S1##0, bs); ds = fmaf(w, hd##S1##0, ds); \
      ws += 1.f; bs += hb##S2##0; ds += hd##S2##0; \
      u = fmaf(z##S3##0, rz, -1.f); a = __saturatef(u*u); w = fex2(fmaf(a, c2l, sw1)); \
      ws += w; bs = fmaf(w, hb##S3##0, bs); ds = fmaf(w, hd##S3##0, ds); \
      u = fmaf(z##S4##0, rz, -1.f); a = __saturatef(u*u); w = fex2(fmaf(a, c2l, sw0)); \
      ws += w; bs = fmaf(w, hb##S4##0, bs); ds = fmaf(w, hd##S4##0, ds); \
      const float wi = frcp(ws); \
      const float bmean = bs * wi, dmean = ds * wi; \
      const float devb = fex2(de * flg2(fmaxf(fabsf(cb.x - bmean), 1e-8f))) * ce; \
      const float devd = fmaxf(fex2(de * flg2(fmaxf(fabsf(cd.x - dmean), 1e-8f))), eps); \
      o0 = (devd * cb.x + devb * cd.x) * frcp(devb + devd); } \
    { const float rz = frcp(z##S2##1); \
      float u, a, w; \
      u = fmaf(z##S0##1, rz, -1.f); a = __saturatef(u*u); w = fex2(fmaf(a, c2l, sw0)); \
      float ws = w, bs = w*hb##S0##1, ds = w*hd##S0##1; \
      u = fmaf(z##S1##1, rz, -1.f); a = __saturatef(u*u); w = fex2(fmaf(a, c2l, sw1)); \
      ws += w; bs = fmaf(w, hb##S1##1, bs); ds = fmaf(w, hd##S1##1, ds); \
      ws += 1.f; bs += hb##S2##1; ds += hd##S2##1; \
      u = fmaf(z##S3##1, rz, -1.f); a = __saturatef(u*u); w = fex2(fmaf(a, c2l, sw1)); \
      ws += w; bs = fmaf(w, hb##S3##1, bs); ds = fmaf(w, hd##S3##1, ds); \
      u = fmaf(z##S4##1, rz, -1.f); a = __saturatef(u*u); w = fex2(fmaf(a, c2l, sw0)); \
      ws += w; bs = fmaf(w, hb##S4##1, bs); ds = fmaf(w, hd##S4##1, ds); \
      const float wi = frcp(ws); \
      const float bmean = bs * wi, dmean = ds * wi; \
      const float devb = fex2(de * flg2(fmaxf(fabsf(cb.y - bmean), 1e-8f))) * ce; \
      const float devd = fmaxf(fex2(de * flg2(fmaxf(fabsf(cd.y - dmean), 1e-8f))), eps); \
      o1 = (devd * cb.y + devb * cd.y) * frcp(devb + devd); } \
    if (yin & stcol) { *(float2*)(po + off) = make_float2(o0, o1); } \
} while(0)

__global__ __launch_bounds__(32, 26)
void bilateral_kernel(const float* __restrict__ bright,
                      const float* __restrict__ dark,
                      const float* __restrict__ depths,
                      const float* __restrict__ s_dv,
                      const float* __restrict__ s_sv,
                      const float* __restrict__ s_de,
                      const float* __restrict__ s_eps,
                      const float* __restrict__ s_ce,
                      float* __restrict__ out)
{
    const int lane = threadIdx.x;
    const int ys = blockIdx.y;                 // 0..24, strip of 42 output rows
    const int xs = blockIdx.x;                 // 0..17, strip of 60 output cols
    const int r0 = ys * 42;                    // first output row (42 % 7 == 0)
    const int gx = xs * 60 - 2 + 2 * lane;     // col of this lane's px0 (even)
    const size_t base = (size_t)blockIdx.z << 20;

    const bool colok = (unsigned)gx < 1024u;   // gx even -> gx+1 in-image too
    const bool stcol = (lane >= 1) & (lane <= 30) & colok;

    const float log2e = 1.44269504f;
    const float c2l = -0.5f * frcp(s_dv[0]) * log2e;
    const float svl = -0.5f * frcp(s_sv[0]) * log2e;
    const float sw0 = 4.f * svl, sw1 = svl;    // spatial exps (base-2); center = 0
    const float de = s_de[0], eps = s_eps[0], ce = s_ce[0];

    const float* pb = bright + base + gx;
    const float* pd = dark   + base + gx;
    const float* pz = depths + base + gx;
    float*       po = out    + base + gx;

    // slot letter X holds the row r with r mod 7 == index(X), A=0 .. G=6
    DECL_SLOT(A) DECL_SLOT(B) DECL_SLOT(C) DECL_SLOT(D) DECL_SLOT(E) DECL_SLOT(F) DECL_SLOT(G)
    float2 pfb, pfd, pfz;      // prefetched padded row

    // prologue: fill slots with rows r0-2 .. r0+3, prefetch r0+4
    LOADROW(r0 - 2);
    STEPC(F, r0 - 2); LOADROW(r0 - 1);
    STEPC(G, r0 - 1); LOADROW(r0    );
    STEPC(A, r0    ); LOADROW(r0 + 1);
    STEPC(B, r0 + 1); LOADROW(r0 + 2);
    STEPC(C, r0 + 2); LOADROW(r0 + 3);
    STEPC(D, r0 + 3); LOADROW(r0 + 4);

    // rotations of 7 rows: STEPC runs 4 rows ahead of EMIT, so every EMIT tap
    // was produced at least 2 full phases earlier.
    const int nrot = min(6, (1024 - r0 + 6) / 7);
    #pragma unroll 1
    for (int it = 0; it < nrot; it++) {
        const int g = r0 + it * 7;
        STEPC(E, g + 4);  LOADROW(g + 5);  EMIT(F, G, A, B, C, g    );
        STEPC(F, g + 5);  LOADROW(g + 6);  EMIT(G, A, B, C, D, g + 1);
        STEPC(G, g + 6);  LOADROW(g + 7);  EMIT(A, B, C, D, E, g + 2);
        STEPC(A, g + 7);  LOADROW(g + 8);  EMIT(B, C, D, E, F, g + 3);
        STEPC(B, g + 8);  LOADROW(g + 9);  EMIT(C, D, E, F, G, g + 4);
        STEPC(C, g + 9);  LOADROW(g + 10); EMIT(D, E, F, G, A, g + 5);
        STEPC(D, g + 10); LOADROW(g + 11); EMIT(E, F, G, A, B, g + 6);
    }
}

extern "C" void kernel_launch(void* const* d_in, const int* in_sizes, int n_in,
                              void* d_out, int out_size)
{
    const float* bright = (const float*)d_in[0];
    const float* dark   = (const float*)d_in[1];
    const float* depths = (const float*)d_in[2];
    const float* s_dv   = (const float*)d_in[3];
    const float* s_sv   = (const float*)d_in[4];
    const float* s_de   = (const float*)d_in[5];
    const float* s_eps  = (const float*)d_in[6];
    const float* s_ce   = (const float*)d_in[7];
    float* out = (float*)d_out;

    const int B = in_sizes[0] / (1024 * 1024);
    // 18 x-strips of 60 cols, 25 y-strips of 42 rows: 3600 one-warp CTAs
    // (single wave at 26 CTAs/SM: capacity 148*26 = 3848; reg cap 78)
    dim3 grid(18, 25, B);
    bilateral_kernel<<<grid, 32>>>(bright, dark, depths,
                                   s_dv, s_sv, s_de, s_eps, s_ce, out);
}

// round 15
// speedup vs baseline: 1.2545x; 1.2545x over previous
#include <cuda_runtime.h>

__device__ __forceinline__ float frcp(float x){ float y; asm("rcp.approx.ftz.f32 %0,%1;":"=f"(y):"f"(x)); return y; }
__device__ __forceinline__ float fex2(float x){ float y; asm("ex2.approx.ftz.f32 %0,%1;":"=f"(y):"f"(x)); return y; }
__device__ __forceinline__ float flg2(float x){ float y; asm("lg2.approx.ftz.f32 %0,%1;":"=f"(y):"f"(x)); return y; }

#define FM 0xFFFFFFFFu

#define DECL_SLOT(S) float hb##S##0, hd##S##0, hb##S##1, hd##S##1, z##S##0, z##S##1;

// Prefetch one padded row (b,d,z) into pfb/pfd/pfz.
#define LOADROW(g) do { \
    const int gg = (g); \
    const bool p = ((unsigned)gg < 1024u) & colok; \
    const size_t off = (size_t)gg << 10; \
    pfb = p ? *(const float2*)(pb + off) : make_float2(0.f, 0.f); \
    pfd = p ? *(const float2*)(pd + off) : make_float2(0.f, 0.f); \
    pfz = p ? *(const float2*)(pz + off) : make_float2(0.f, 0.f); \
} while(0)

// Horizontal blur of prefetched row; tree-form accumulation (short dep chains).
#define STEPC(S, g) do { \
    const bool yin = (unsigned)(g) < 1024u; \
    const float bx=pfb.x, by=pfb.y, dx=pfd.x, dy=pfd.y, zx=pfz.x, zy=pfz.y; \
    const float blx = __shfl_up_sync(FM, bx, 1); \
    const float bly = __shfl_up_sync(FM, by, 1); \
    const float dlx = __shfl_up_sync(FM, dx, 1); \
    const float dly = __shfl_up_sync(FM, dy, 1); \
    const float zlx = __shfl_up_sync(FM, zx, 1); \
    const float zly = __shfl_up_sync(FM, zy, 1); \
    const float brx = __shfl_down_sync(FM, bx, 1); \
    const float bry = __shfl_down_sync(FM, by, 1); \
    const float drx = __shfl_down_sync(FM, dx, 1); \
    const float dry = __shfl_down_sync(FM, dy, 1); \
    const float zrx = __shfl_down_sync(FM, zx, 1); \
    const float zry = __shfl_down_sync(FM, zy, 1); \
    { /* px0 */ \
      const float rz = frcp(zx); \
      float u0 = fmaf(zlx, rz, -1.f); float a0 = __saturatef(u0*u0); \
      float u1 = fmaf(zly, rz, -1.f); float a1 = __saturatef(u1*u1); \
      float u3 = fmaf(zy , rz, -1.f); float a3 = __saturatef(u3*u3); \
      float u4 = fmaf(zrx, rz, -1.f); float a4 = __saturatef(u4*u4); \
      const float w0 = fex2(fmaf(a0, c2l, sw0)); \
      const float w1 = fex2(fmaf(a1, c2l, sw1)); \
      const float w3 = fex2(fmaf(a3, c2l, sw1)); \
      const float w4 = fex2(fmaf(a4, c2l, sw0)); \
      const float ws = (w0 + w1) + ((1.f + w3) + w4); /* center tap w==1 */ \
      const float bs = fmaf(w1, bly, w0*blx) + fmaf(w4, brx, fmaf(w3, by, bx)); \
      const float ds = fmaf(w1, dly, w0*dlx) + fmaf(w4, drx, fmaf(w3, dy, dx)); \
      const float wi = yin ? frcp(ws) : 0.f; \
      hb##S##0 = bs * wi; hd##S##0 = ds * wi; } \
    { /* px1 */ \
      const float rz = frcp(zy); \
      float u0 = fmaf(zly, rz, -1.f); float a0 = __saturatef(u0*u0); \
      float u1 = fmaf(zx , rz, -1.f); float a1 = __saturatef(u1*u1); \
      float u3 = fmaf(zrx, rz, -1.f); float a3 = __saturatef(u3*u3); \
      float u4 = fmaf(zry, rz, -1.f); float a4 = __saturatef(u4*u4); \
      const float w0 = fex2(fmaf(a0, c2l, sw0)); \
      const float w1 = fex2(fmaf(a1, c2l, sw1)); \
      const float w3 = fex2(fmaf(a3, c2l, sw1)); \
      const float w4 = fex2(fmaf(a4, c2l, sw0)); \
      const float ws = (w0 + w1) + ((1.f + w3) + w4); \
      const float bs = fmaf(w1, bx, w0*bly) + fmaf(w4, bry, fmaf(w3, brx, by)); \
      const float ds = fmaf(w1, dx, w0*dly) + fmaf(w4, dry, fmaf(w3, drx, dy)); \
      const float wi = yin ? frcp(ws) : 0.f; \
      hb##S##1 = bs * wi; hd##S##1 = ds * wi; } \
    z##S##0 = zx; z##S##1 = zy; \
} while(0)

// Vertical blur + blend + store; tree-form accumulation. Center b/d loaded
// here (L1-hit: lines fetched by LOADROW(g) phases earlier). Slot inputs are
// >= 1 full phase old -> independent of same-phase STEPC.
#define EMIT(S0,S1,S2,S3,S4, g) do { \
    const int gg = (g); \
    const bool yin = (unsigned)gg < 1024u; \
    const size_t off = (size_t)gg << 10; \
    const bool cp = yin & colok; \
    const float2 cb = cp ? *(const float2*)(pb + off) : make_float2(0.f, 0.f); \
    const float2 cd = cp ? *(const float2*)(pd + off) : make_float2(0.f, 0.f); \
    float o0, o1; \
    { const float rz = frcp(z##S2##0); \
      float u0 = fmaf(z##S0##0, rz, -1.f); float a0 = __saturatef(u0*u0); \
      float u1 = fmaf(z##S1##0, rz, -1.f); float a1 = __saturatef(u1*u1); \
      float u3 = fmaf(z##S3##0, rz, -1.f); float a3 = __saturatef(u3*u3); \
      float u4 = fmaf(z##S4##0, rz, -1.f); float a4 = __saturatef(u4*u4); \
      const float w0 = fex2(fmaf(a0, c2l, sw0)); \
      const float w1 = fex2(fmaf(a1, c2l, sw1)); \
      const float w3 = fex2(fmaf(a3, c2l, sw1)); \
      const float w4 = fex2(fmaf(a4, c2l, sw0)); \
      const float ws = (w0 + w1) + ((1.f + w3) + w4); \
      const float bs = fmaf(w1, hb##S1##0, w0*hb##S0##0) \
                     + fmaf(w4, hb##S4##0, fmaf(w3, hb##S3##0, hb##S2##0)); \
      const float ds = fmaf(w1, hd##S1##0, w0*hd##S0##0) \
                     + fmaf(w4, hd##S4##0, fmaf(w3, hd##S3##0, hd##S2##0)); \
      const float wi = frcp(ws); \
      const float bmean = bs * wi, dmean = ds * wi; \
      const float devb = fex2(de * flg2(fmaxf(fabsf(cb.x - bmean), 1e-8f))) * ce; \
      const float devd = fmaxf(fex2(de * flg2(fmaxf(fabsf(cd.x - dmean), 1e-8f))), eps); \
      o0 = (devd * cb.x + devb * cd.x) * frcp(devb + devd); } \
    { const float rz = frcp(z##S2##1); \
      float u0 = fmaf(z##S0##1, rz, -1.f); float a0 = __saturatef(u0*u0); \
      float u1 = fmaf(z##S1##1, rz, -1.f); float a1 = __saturatef(u1*u1); \
      float u3 = fmaf(z##S3##1, rz, -1.f); float a3 = __saturatef(u3*u3); \
      float u4 = fmaf(z##S4##1, rz, -1.f); float a4 = __saturatef(u4*u4); \
      const float w0 = fex2(fmaf(a0, c2l, sw0)); \
      const float w1 = fex2(fmaf(a1, c2l, sw1)); \
      const float w3 = fex2(fmaf(a3, c2l, sw1)); \
      const float w4 = fex2(fmaf(a4, c2l, sw0)); \
      const float ws = (w0 + w1) + ((1.f + w3) + w4); \
      const float bs = fmaf(w1, hb##S1##1, w0*hb##S0##1) \
                     + fmaf(w4, hb##S4##1, fmaf(w3, hb##S3##1, hb##S2##1)); \
      const float ds = fmaf(w1, hd##S1##1, w0*hd##S0##1) \
                     + fmaf(w4, hd##S4##1, fmaf(w3, hd##S3##1, hd##S2##1)); \
      const float wi = frcp(ws); \
      const float bmean = bs * wi, dmean = ds * wi; \
      const float devb = fex2(de * flg2(fmaxf(fabsf(cb.y - bmean), 1e-8f))) * ce; \
      const float devd = fmaxf(fex2(de * flg2(fmaxf(fabsf(cd.y - dmean), 1e-8f))), eps); \
      o1 = (devd * cb.y + devb * cd.y) * frcp(devb + devd); } \
    if (yin & stcol) { *(float2*)(po + off) = make_float2(o0, o1); } \
} while(0)

__global__ __launch_bounds__(32, 28)
void bilateral_kernel(const float* __restrict__ bright,
                      const float* __restrict__ dark,
                      const float* __restrict__ depths,
                      const float* __restrict__ s_dv,
                      const float* __restrict__ s_sv,
                      const float* __restrict__ s_de,
                      const float* __restrict__ s_eps,
                      const float* __restrict__ s_ce,
                      float* __restrict__ out)
{
    const int lane = threadIdx.x;
    const int ys = blockIdx.y;                 // 0..24, strip of 42 output rows
    const int xs = blockIdx.x;                 // 0..17, strip of 60 output cols
    const int r0 = ys * 42;                    // first output row
    const int gx = xs * 60 - 2 + 2 * lane;     // col of this lane's px0 (even)
    const size_t base = (size_t)blockIdx.z << 20;

    const bool colok = (unsigned)gx < 1024u;   // gx even -> gx+1 in-image too
    const bool stcol = (lane >= 1) & (lane <= 30) & colok;

    const float log2e = 1.44269504f;
    const float c2l = -0.5f * frcp(s_dv[0]) * log2e;
    const float svl = -0.5f * frcp(s_sv[0]) * log2e;
    const float sw0 = 4.f * svl, sw1 = svl;    // spatial exps (base-2); center = 0
    const float de = s_de[0], eps = s_eps[0], ce = s_ce[0];

    const float* pb = bright + base + gx;
    const float* pd = dark   + base + gx;
    const float* pz = depths + base + gx;
    float*       po = out    + base + gx;

    DECL_SLOT(A) DECL_SLOT(B) DECL_SLOT(C) DECL_SLOT(D) DECL_SLOT(E) DECL_SLOT(F)
    float2 pfb, pfd, pfz;      // prefetched padded row

    // prologue: fill slots A..E with rows r0-2 .. r0+2, prefetch r0+3
    LOADROW(r0 - 2);
    STEPC(A, r0 - 2); LOADROW(r0 - 1);
    STEPC(B, r0 - 1); LOADROW(r0    );
    STEPC(C, r0    ); LOADROW(r0 + 1);
    STEPC(D, r0 + 1); LOADROW(r0 + 2);
    STEPC(E, r0 + 2); LOADROW(r0 + 3);

    // rotations of 6 rows: each phase's STEPC target slot is unused by that
    // phase's EMIT, and the EMIT's newest tap is one full phase old -> ILP.
    const int nrot = min(7, (1024 - r0 + 5) / 6);
    #pragma unroll 1
    for (int it = 0; it < nrot; it++) {
        const int g = r0 + it * 6;
        STEPC(F, g + 3); LOADROW(g + 4); EMIT(A, B, C, D, E, g    );
        STEPC(A, g + 4); LOADROW(g + 5); EMIT(B, C, D, E, F, g + 1);
        STEPC(B, g + 5); LOADROW(g + 6); EMIT(C, D, E, F, A, g + 2);
        STEPC(C, g + 6); LOADROW(g + 7); EMIT(D, E, F, A, B, g + 3);
        STEPC(D, g + 7); LOADROW(g + 8); EMIT(E, F, A, B, C, g + 4);
        STEPC(E, g + 8); LOADROW(g + 9); EMIT(F, A, B, C, D, g + 5);
    }
}

extern "C" void kernel_launch(void* const* d_in, const int* in_sizes, int n_in,
                              void* d_out, int out_size)
{
    const float* bright = (const float*)d_in[0];
    const float* dark   = (const float*)d_in[1];
    const float* depths = (const float*)d_in[2];
    const float* s_dv   = (const float*)d_in[3];
    const float* s_sv   = (const float*)d_in[4];
    const float* s_de   = (const float*)d_in[5];
    const float* s_eps  = (const float*)d_in[6];
    const float* s_ce   = (const float*)d_in[7];
    float* out = (float*)d_out;

    const int B = in_sizes[0] / (1024 * 1024);
    // 18 x-strips of 60 cols, 25 y-strips of 42 rows: 3600 one-warp CTAs
    // (single wave at 28 CTAs/SM: capacity 148*28 = 4144)
    dim3 grid(18, 25, B);
    bilateral_kernel<<<grid, 32>>>(bright, dark, depths,
                                   s_dv, s_sv, s_de, s_eps, s_ce, out);
}